// round 1
// baseline (speedup 1.0000x reference)
#include <cuda_runtime.h>
#include <cstddef>

#define DIM   768
#define NQKV  2304
#define BATCH 16
#define SEQ   1024
#define HEADS 12
#define HD    64
#define BH    (BATCH*HEADS)     // 192
#define MTOT  (BATCH*SEQ)       // 16384

// Scratch (allocation-free rule: __device__ globals)
__device__ float g_Q[(size_t)BH*SEQ*HD];
__device__ float g_K[(size_t)BH*SEQ*HD];
__device__ float g_V[(size_t)BH*SEQ*HD];
__device__ float g_O[(size_t)MTOT*DIM];

// ---------------------------------------------------------------------------
// QKV GEMM: C[16384,2304] = X[16384,768] @ Wqkv + b, scattered into Q/K/V
// laid out as [bh][n][64]. Block tile 64x64, 256 threads, 4x4 micro-tile.
// Each 64-wide column tile is exactly one (which, head) pair.
// ---------------------------------------------------------------------------
__global__ __launch_bounds__(256) void qkv_gemm_kernel(
    const float* __restrict__ X, const float* __restrict__ W,
    const float* __restrict__ bias)
{
    __shared__ float As[16][65];   // [k][m], padded
    __shared__ float Ws[16][64];   // [k][n]

    const int tid = threadIdx.x;
    const int tx = tid & 15, ty = tid >> 4;
    const int m0 = blockIdx.y * 64;
    const int n0 = blockIdx.x * 64;

    float acc[4][4] = {};

    for (int k0 = 0; k0 < DIM; k0 += 16) {
        #pragma unroll
        for (int e = 0; e < 4; e++) {
            int p = tid + e * 256;            // 0..1023
            int mm = p >> 4, kk = p & 15;
            As[kk][mm] = X[(size_t)(m0 + mm) * DIM + k0 + kk];
        }
        {
            int kk = tid >> 4, nn = (tid & 15) * 4;
            float4 w4 = *(const float4*)&W[(size_t)(k0 + kk) * NQKV + n0 + nn];
            Ws[kk][nn] = w4.x; Ws[kk][nn+1] = w4.y;
            Ws[kk][nn+2] = w4.z; Ws[kk][nn+3] = w4.w;
        }
        __syncthreads();

        #pragma unroll
        for (int kk = 0; kk < 16; kk++) {
            float a[4], b[4];
            #pragma unroll
            for (int i = 0; i < 4; i++) a[i] = As[kk][ty*4 + i];
            #pragma unroll
            for (int j = 0; j < 4; j++) b[j] = Ws[kk][tx*4 + j];
            #pragma unroll
            for (int i = 0; i < 4; i++)
                #pragma unroll
                for (int j = 0; j < 4; j++)
                    acc[i][j] += a[i] * b[j];
        }
        __syncthreads();
    }

    // Epilogue: bias + scatter. n0 is 64-aligned -> single (which, head).
    const int which = n0 / DIM;
    const int h = (n0 % DIM) / HD;
    float* dst = (which == 0) ? g_Q : (which == 1) ? g_K : g_V;

    float bv[4];
    #pragma unroll
    for (int j = 0; j < 4; j++) bv[j] = bias[n0 + tx*4 + j];

    #pragma unroll
    for (int i = 0; i < 4; i++) {
        int m = m0 + ty*4 + i;
        int b = m / SEQ, n = m % SEQ;
        float* row = dst + ((size_t)(b * HEADS + h) * SEQ + n) * HD;
        #pragma unroll
        for (int j = 0; j < 4; j++)
            row[tx*4 + j] = acc[i][j] + bv[j];
    }
}

// ---------------------------------------------------------------------------
// Flash attention: block = (bh, 64-query tile), 256 threads.
// smem: Q,K,V,S tiles [64][65] + row stats. Online softmax by threads 0..63.
// Output written to g_O as [b][n][h*64+d] (i.e. [16384,768]).
// ---------------------------------------------------------------------------
#define ATTN_SMEM_FLOATS (4*64*65 + 3*64)
#define ATTN_SMEM_BYTES  (ATTN_SMEM_FLOATS * 4)

__global__ __launch_bounds__(256) void attn_kernel()
{
    extern __shared__ float sm[];
    float* Qs = sm;                 // 64*65
    float* Ks = Qs + 64*65;
    float* Vs = Ks + 64*65;
    float* Ss = Vs + 64*65;
    float* mrow = Ss + 64*65;       // 64
    float* lrow = mrow + 64;        // 64
    float* arow = lrow + 64;        // 64

    const int tid = threadIdx.x;
    const int tx = tid & 15, ty = tid >> 4;
    const int bh = blockIdx.y;
    const int q0 = blockIdx.x * 64;

    const float* Qg = g_Q + (size_t)bh * SEQ * HD;
    const float* Kg = g_K + (size_t)bh * SEQ * HD;
    const float* Vg = g_V + (size_t)bh * SEQ * HD;

    // Load Q tile (64x64) as float4
    #pragma unroll
    for (int e = 0; e < 4; e++) {
        int p = tid + e * 256;              // 1024 float4 slots
        int r = p >> 4, c4 = (p & 15) * 4;
        float4 v = *(const float4*)&Qg[(size_t)(q0 + r) * HD + c4];
        Qs[r*65 + c4]   = v.x; Qs[r*65 + c4+1] = v.y;
        Qs[r*65 + c4+2] = v.z; Qs[r*65 + c4+3] = v.w;
    }
    if (tid < 64) { mrow[tid] = -1e30f; lrow[tid] = 0.0f; }

    float acc[4][4] = {};
    __syncthreads();

    for (int t = 0; t < SEQ / 64; t++) {
        // Load K, V tiles
        #pragma unroll
        for (int e = 0; e < 4; e++) {
            int p = tid + e * 256;
            int r = p >> 4, c4 = (p & 15) * 4;
            size_t off = (size_t)(t*64 + r) * HD + c4;
            float4 kv = *(const float4*)&Kg[off];
            Ks[r*65 + c4]   = kv.x; Ks[r*65 + c4+1] = kv.y;
            Ks[r*65 + c4+2] = kv.z; Ks[r*65 + c4+3] = kv.w;
            float4 vv = *(const float4*)&Vg[off];
            Vs[r*65 + c4]   = vv.x; Vs[r*65 + c4+1] = vv.y;
            Vs[r*65 + c4+2] = vv.z; Vs[r*65 + c4+3] = vv.w;
        }
        __syncthreads();

        // S = scale * Q @ K^T  (64x64)
        float s[4][4] = {};
        #pragma unroll 8
        for (int d = 0; d < 64; d++) {
            float a[4], k[4];
            #pragma unroll
            for (int i = 0; i < 4; i++) a[i] = Qs[(ty*4 + i)*65 + d];
            #pragma unroll
            for (int j = 0; j < 4; j++) k[j] = Ks[(tx*4 + j)*65 + d];
            #pragma unroll
            for (int i = 0; i < 4; i++)
                #pragma unroll
                for (int j = 0; j < 4; j++)
                    s[i][j] += a[i] * k[j];
        }
        #pragma unroll
        for (int i = 0; i < 4; i++)
            #pragma unroll
            for (int j = 0; j < 4; j++)
                Ss[(ty*4 + i)*65 + tx*4 + j] = s[i][j] * 0.125f;
        __syncthreads();

        // Online softmax per row (threads 0..63, one row each; conflict-free:
        // stride 65 -> bank = (row + c) % 32 distinct across the warp)
        if (tid < 64) {
            float mold = mrow[tid];
            float tm = mold;
            #pragma unroll 16
            for (int c = 0; c < 64; c++) tm = fmaxf(tm, Ss[tid*65 + c]);
            float alpha = __expf(mold - tm);
            float sum = 0.0f;
            #pragma unroll 16
            for (int c = 0; c < 64; c++) {
                float p = __expf(Ss[tid*65 + c] - tm);
                Ss[tid*65 + c] = p;
                sum += p;
            }
            lrow[tid] = lrow[tid] * alpha + sum;
            mrow[tid] = tm;
            arow[tid] = alpha;
        }
        __syncthreads();

        // Rescale acc, then acc += P @ V
        float al[4];
        #pragma unroll
        for (int i = 0; i < 4; i++) al[i] = arow[ty*4 + i];
        #pragma unroll
        for (int i = 0; i < 4; i++)
            #pragma unroll
            for (int j = 0; j < 4; j++)
                acc[i][j] *= al[i];

        #pragma unroll 8
        for (int c = 0; c < 64; c++) {
            float p[4], v[4];
            #pragma unroll
            for (int i = 0; i < 4; i++) p[i] = Ss[(ty*4 + i)*65 + c];
            #pragma unroll
            for (int j = 0; j < 4; j++) v[j] = Vs[c*65 + tx*4 + j];
            #pragma unroll
            for (int i = 0; i < 4; i++)
                #pragma unroll
                for (int j = 0; j < 4; j++)
                    acc[i][j] += p[i] * v[j];
        }
        __syncthreads();
    }

    // Normalize + write [b][n][h*64+d]
    const int b = bh / HEADS, h = bh % HEADS;
    #pragma unroll
    for (int i = 0; i < 4; i++) {
        int n = q0 + ty*4 + i;
        float inv = 1.0f / lrow[ty*4 + i];
        float* orow = g_O + ((size_t)b * SEQ + n) * DIM + h * HD;
        #pragma unroll
        for (int j = 0; j < 4; j++)
            orow[tx*4 + j] = acc[i][j] * inv;
    }
}

// ---------------------------------------------------------------------------
// Proj GEMM: out[16384,768] = g_O @ Wproj + bias
// ---------------------------------------------------------------------------
__global__ __launch_bounds__(256) void proj_gemm_kernel(
    const float* __restrict__ W, const float* __restrict__ bias,
    float* __restrict__ out)
{
    __shared__ float As[16][65];
    __shared__ float Ws[16][64];

    const int tid = threadIdx.x;
    const int tx = tid & 15, ty = tid >> 4;
    const int m0 = blockIdx.y * 64;
    const int n0 = blockIdx.x * 64;

    float acc[4][4] = {};

    for (int k0 = 0; k0 < DIM; k0 += 16) {
        #pragma unroll
        for (int e = 0; e < 4; e++) {
            int p = tid + e * 256;
            int mm = p >> 4, kk = p & 15;
            As[kk][mm] = g_O[(size_t)(m0 + mm) * DIM + k0 + kk];
        }
        {
            int kk = tid >> 4, nn = (tid & 15) * 4;
            float4 w4 = *(const float4*)&W[(size_t)(k0 + kk) * DIM + n0 + nn];
            Ws[kk][nn] = w4.x; Ws[kk][nn+1] = w4.y;
            Ws[kk][nn+2] = w4.z; Ws[kk][nn+3] = w4.w;
        }
        __syncthreads();

        #pragma unroll
        for (int kk = 0; kk < 16; kk++) {
            float a[4], b[4];
            #pragma unroll
            for (int i = 0; i < 4; i++) a[i] = As[kk][ty*4 + i];
            #pragma unroll
            for (int j = 0; j < 4; j++) b[j] = Ws[kk][tx*4 + j];
            #pragma unroll
            for (int i = 0; i < 4; i++)
                #pragma unroll
                for (int j = 0; j < 4; j++)
                    acc[i][j] += a[i] * b[j];
        }
        __syncthreads();
    }

    float bv[4];
    #pragma unroll
    for (int j = 0; j < 4; j++) bv[j] = bias[n0 + tx*4 + j];

    #pragma unroll
    for (int i = 0; i < 4; i++) {
        int m = m0 + ty*4 + i;
        #pragma unroll
        for (int j = 0; j < 4; j++)
            out[(size_t)m * DIM + n0 + tx*4 + j] = acc[i][j] + bv[j];
    }
}

// ---------------------------------------------------------------------------
extern "C" void kernel_launch(void* const* d_in, const int* in_sizes, int n_in,
                              void* d_out, int out_size)
{
    (void)in_sizes; (void)n_in; (void)out_size;
    const float* x     = (const float*)d_in[0];
    const float* wqkv  = (const float*)d_in[1];
    const float* bqkv  = (const float*)d_in[2];
    const float* wproj = (const float*)d_in[3];
    const float* bproj = (const float*)d_in[4];
    float* out = (float*)d_out;

    cudaFuncSetAttribute(attn_kernel,
                         cudaFuncAttributeMaxDynamicSharedMemorySize,
                         ATTN_SMEM_BYTES);

    dim3 g1(NQKV / 64, MTOT / 64);   // 36 x 256
    qkv_gemm_kernel<<<g1, 256>>>(x, wqkv, bqkv);

    dim3 g2(SEQ / 64, BH);           // 16 x 192
    attn_kernel<<<g2, 256, ATTN_SMEM_BYTES>>>();

    dim3 g3(DIM / 64, MTOT / 64);    // 12 x 256
    proj_gemm_kernel<<<g3, 256>>>(wproj, bproj, out);
}

// round 3
// speedup vs baseline: 2.0708x; 2.0708x over previous
#include <cuda_runtime.h>
#include <cuda_bf16.h>
#include <cstdint>
#include <cstddef>

#define DIM   768
#define NQKV  2304
#define BATCH 16
#define SEQ   1024
#define HEADS 12
#define HD    64
#define BH    (BATCH*HEADS)     // 192
#define MTOT  (BATCH*SEQ)       // 16384

using bf16 = __nv_bfloat16;

// Scratch: Q/K/V/O stored as bf16 hi/lo split pairs (allocation-free rule)
__device__ __align__(16) bf16 g_Qh[(size_t)BH*SEQ*HD];
__device__ __align__(16) bf16 g_Ql[(size_t)BH*SEQ*HD];
__device__ __align__(16) bf16 g_Kh[(size_t)BH*SEQ*HD];
__device__ __align__(16) bf16 g_Kl[(size_t)BH*SEQ*HD];
__device__ __align__(16) bf16 g_Vh[(size_t)BH*SEQ*HD];
__device__ __align__(16) bf16 g_Vl[(size_t)BH*SEQ*HD];
__device__ __align__(16) bf16 g_Oh[(size_t)MTOT*DIM];
__device__ __align__(16) bf16 g_Ol[(size_t)MTOT*DIM];

// ---------------------------------------------------------------------------
// helpers
// ---------------------------------------------------------------------------
__device__ __forceinline__ uint32_t cvta_s(const void* p) {
    return (uint32_t)__cvta_generic_to_shared(p);
}
__device__ __forceinline__ void ldmx4(uint32_t* r, uint32_t a) {
    asm volatile("ldmatrix.sync.aligned.m8n8.x4.shared.b16 {%0,%1,%2,%3},[%4];\n"
        : "=r"(r[0]), "=r"(r[1]), "=r"(r[2]), "=r"(r[3]) : "r"(a));
}
__device__ __forceinline__ void ldmx2(uint32_t& r0, uint32_t& r1, uint32_t a) {
    asm volatile("ldmatrix.sync.aligned.m8n8.x2.shared.b16 {%0,%1},[%2];\n"
        : "=r"(r0), "=r"(r1) : "r"(a));
}
__device__ __forceinline__ void ldmx2t(uint32_t& r0, uint32_t& r1, uint32_t a) {
    asm volatile("ldmatrix.sync.aligned.m8n8.x2.trans.shared.b16 {%0,%1},[%2];\n"
        : "=r"(r0), "=r"(r1) : "r"(a));
}
__device__ __forceinline__ void mma_bf16(float* c, const uint32_t* a,
                                         uint32_t b0, uint32_t b1) {
    asm volatile(
        "mma.sync.aligned.m16n8k16.row.col.f32.bf16.bf16.f32 "
        "{%0,%1,%2,%3},{%4,%5,%6,%7},{%8,%9},{%0,%1,%2,%3};\n"
        : "+f"(c[0]), "+f"(c[1]), "+f"(c[2]), "+f"(c[3])
        : "r"(a[0]), "r"(a[1]), "r"(a[2]), "r"(a[3]), "r"(b0), "r"(b1));
}
__device__ __forceinline__ uint32_t packbf(bf16 a, bf16 b) {
    return (uint32_t)__bfloat16_as_ushort(a) |
           ((uint32_t)__bfloat16_as_ushort(b) << 16);
}
__device__ __forceinline__ void split1(float x, bf16& h, bf16& l) {
    h = __float2bfloat16_rn(x);
    l = __float2bfloat16_rn(x - __bfloat162float(h));
}
__device__ __forceinline__ void split_pair(float a, float b,
                                           uint32_t& H, uint32_t& L) {
    bf16 ha, la, hb, lb;
    split1(a, ha, la);
    split1(b, hb, lb);
    H = packbf(ha, hb);
    L = packbf(la, lb);
}

// ---------------------------------------------------------------------------
// QKV GEMM: C[16384,2304] = X @ Wqkv + b, written as bf16 hi/lo split into
// g_{Q,K,V}{h,l} with layout [bh][seq][64]. Q pre-scaled by 1/8.
// Block 128m x 64n, 256 thr (8 warps as 4x2), k-chunk 32, bf16x3 mma.
// ---------------------------------------------------------------------------
#define AP 40   // smem row pad: 32 + 8 bf16 (80B = 5x16B, ldmatrix conflict-free)

__global__ __launch_bounds__(256) void qkv_gemm(
    const float* __restrict__ X, const float* __restrict__ W,
    const float* __restrict__ bias)
{
    __shared__ __align__(16) bf16 Ah[128*AP], Al[128*AP];
    __shared__ __align__(16) bf16 Bh[64*AP],  Bl[64*AP];

    const int tid = threadIdx.x, lane = tid & 31, wid = tid >> 5;
    const int wm = (wid & 3)*32, wn = (wid >> 2)*32;
    const int m0 = blockIdx.y*128;
    const int bx = blockIdx.x, n0 = bx*64;

    float c[2][4][4];
    #pragma unroll
    for (int i = 0; i < 2; i++)
        #pragma unroll
        for (int j = 0; j < 4; j++)
            #pragma unroll
            for (int k = 0; k < 4; k++) c[i][j][k] = 0.f;

    const uint32_t sAh = cvta_s(Ah), sAl = cvta_s(Al);
    const uint32_t sBh = cvta_s(Bh), sBl = cvta_s(Bl);

    for (int k0 = 0; k0 < DIM; k0 += 32) {
        __syncthreads();
        // A tile 128x32 fp32 -> split hi/lo bf16, [m][k] rows padded to AP
        #pragma unroll
        for (int p = 0; p < 4; p++) {
            int idx = p*256 + tid;
            int r = idx >> 3, k4 = (idx & 7)*4;
            float4 v = *(const float4*)&X[(size_t)(m0 + r)*DIM + k0 + k4];
            uint32_t H0, L0, H1, L1;
            split_pair(v.x, v.y, H0, L0);
            split_pair(v.z, v.w, H1, L1);
            uint32_t off = (uint32_t)(r*AP + k4) >> 1;
            ((uint32_t*)Ah)[off]   = H0; ((uint32_t*)Ah)[off+1] = H1;
            ((uint32_t*)Al)[off]   = L0; ((uint32_t*)Al)[off+1] = L1;
        }
        // B tile 32k x 64n fp32 -> transpose-split into [n][k]
        #pragma unroll
        for (int p = 0; p < 2; p++) {
            int idx = p*256 + tid;
            int kk = idx >> 4, n4 = (idx & 15)*4;
            float4 v = *(const float4*)&W[(size_t)(k0 + kk)*NQKV + n0 + n4];
            bf16 h, l;
            split1(v.x, h, l); Bh[(n4+0)*AP + kk] = h; Bl[(n4+0)*AP + kk] = l;
            split1(v.y, h, l); Bh[(n4+1)*AP + kk] = h; Bl[(n4+1)*AP + kk] = l;
            split1(v.z, h, l); Bh[(n4+2)*AP + kk] = h; Bl[(n4+2)*AP + kk] = l;
            split1(v.w, h, l); Bh[(n4+3)*AP + kk] = h; Bl[(n4+3)*AP + kk] = l;
        }
        __syncthreads();

        #pragma unroll
        for (int ks = 0; ks < 2; ks++) {
            uint32_t ah[2][4], al[2][4];
            #pragma unroll
            for (int mt = 0; mt < 2; mt++) {
                uint32_t off = (uint32_t)((wm + mt*16 + (lane & 15))*AP
                               + ks*16 + ((lane >> 4) & 1)*8)*2;
                ldmx4(ah[mt], sAh + off);
                ldmx4(al[mt], sAl + off);
            }
            #pragma unroll
            for (int nt = 0; nt < 4; nt++) {
                uint32_t off = (uint32_t)((wn + nt*8 + (lane & 7))*AP
                               + ks*16 + ((lane >> 3) & 1)*8)*2;
                uint32_t b0, b1, d0, d1;
                ldmx2(b0, b1, sBh + off);
                ldmx2(d0, d1, sBl + off);
                #pragma unroll
                for (int mt = 0; mt < 2; mt++) {
                    mma_bf16(c[mt][nt], ah[mt], b0, b1);
                    mma_bf16(c[mt][nt], ah[mt], d0, d1);
                    mma_bf16(c[mt][nt], al[mt], b0, b1);
                }
            }
        }
    }

    // Epilogue: bias, (Q) scale, split, scatter to [bh][seq][64]
    const int which = bx / 12, hh = bx % 12;
    bf16 *dh, *dl;
    if (which == 0)      { dh = g_Qh; dl = g_Ql; }
    else if (which == 1) { dh = g_Kh; dl = g_Kl; }
    else                 { dh = g_Vh; dl = g_Vl; }
    const float qs = (which == 0) ? 0.125f : 1.0f;

    #pragma unroll
    for (int mt = 0; mt < 2; mt++) {
        int r = m0 + wm + mt*16 + (lane >> 2);
        int bb = r >> 10, ss = r & 1023;
        size_t rowbase = ((size_t)(bb*HEADS + hh)*SEQ + ss)*HD;
        #pragma unroll
        for (int nt = 0; nt < 4; nt++) {
            int col = wn + nt*8 + (lane & 3)*2;
            float b0 = bias[n0 + col], b1 = bias[n0 + col + 1];
            uint32_t H, L;
            split_pair((c[mt][nt][0] + b0)*qs, (c[mt][nt][1] + b1)*qs, H, L);
            ((uint32_t*)dh)[(rowbase + col) >> 1] = H;
            ((uint32_t*)dl)[(rowbase + col) >> 1] = L;
            split_pair((c[mt][nt][2] + b0)*qs, (c[mt][nt][3] + b1)*qs, H, L);
            ((uint32_t*)dh)[(rowbase + (size_t)8*HD + col) >> 1] = H;
            ((uint32_t*)dl)[(rowbase + (size_t)8*HD + col) >> 1] = L;
        }
    }
}

// ---------------------------------------------------------------------------
// Flash attention: block = (q-tile 64, bh), 128 thr (4 warps, 16 q-rows each).
// Key tile 64. S and O accumulated in fp32 mma frags; bf16x3 for both matmuls.
// Output split-written to g_O{h,l} as [b][seq][768].
// ---------------------------------------------------------------------------
#define QP 72                        // 64 + 8 pad (144B = 9x16B)
#define ATTN_SMEM (6*64*QP*2)        // Qh Ql Kh Kl Vh Vl

__global__ __launch_bounds__(128) void attn_kernel()
{
    extern __shared__ __align__(16) bf16 smA[];
    bf16* Qh = smA;
    bf16* Ql = Qh + 64*QP;
    bf16* Kh = Ql + 64*QP;
    bf16* Kl = Kh + 64*QP;
    bf16* Vh = Kl + 64*QP;
    bf16* Vl = Vh + 64*QP;

    const int tid = threadIdx.x, lane = tid & 31, w = tid >> 5;
    const int bh = blockIdx.y, q0 = blockIdx.x*64;
    const int bb = bh / HEADS, hh = bh % HEADS;
    const size_t hoff = (size_t)bh * SEQ * HD;

    // Load Q tile (64x64 bf16 hi/lo)
    {
        const uint4* gh = (const uint4*)(g_Qh + hoff + (size_t)q0*HD);
        const uint4* gl = (const uint4*)(g_Ql + hoff + (size_t)q0*HD);
        #pragma unroll
        for (int p = 0; p < 4; p++) {
            int idx = p*128 + tid;
            int r = idx >> 3, u = idx & 7;
            *(uint4*)&Qh[r*QP + u*8] = gh[idx];
            *(uint4*)&Ql[r*QP + u*8] = gl[idx];
        }
    }
    __syncthreads();

    // Q A-frags into registers (4 k-steps over d=64, hi/lo)
    uint32_t qh[4][4], ql[4][4];
    {
        const uint32_t sQh = cvta_s(Qh), sQl = cvta_s(Ql);
        #pragma unroll
        for (int ks = 0; ks < 4; ks++) {
            uint32_t off = (uint32_t)((w*16 + (lane & 15))*QP
                           + ks*16 + ((lane >> 4) & 1)*8)*2;
            ldmx4(qh[ks], sQh + off);
            ldmx4(ql[ks], sQl + off);
        }
    }

    const uint32_t sKh = cvta_s(Kh), sKl = cvta_s(Kl);
    const uint32_t sVh = cvta_s(Vh), sVl = cvta_s(Vl);

    float o[8][4];
    #pragma unroll
    for (int i = 0; i < 8; i++)
        #pragma unroll
        for (int j = 0; j < 4; j++) o[i][j] = 0.f;
    float mr0 = -1e30f, mr1 = -1e30f, lr0 = 0.f, lr1 = 0.f;

    for (int t = 0; t < SEQ/64; t++) {
        __syncthreads();   // protect previous iteration's V reads
        {
            const uint4* gkh = (const uint4*)(g_Kh + hoff + (size_t)t*64*HD);
            const uint4* gkl = (const uint4*)(g_Kl + hoff + (size_t)t*64*HD);
            const uint4* gvh = (const uint4*)(g_Vh + hoff + (size_t)t*64*HD);
            const uint4* gvl = (const uint4*)(g_Vl + hoff + (size_t)t*64*HD);
            #pragma unroll
            for (int p = 0; p < 4; p++) {
                int idx = p*128 + tid;
                int r = idx >> 3, u = idx & 7;
                *(uint4*)&Kh[r*QP + u*8] = gkh[idx];
                *(uint4*)&Kl[r*QP + u*8] = gkl[idx];
                *(uint4*)&Vh[r*QP + u*8] = gvh[idx];
                *(uint4*)&Vl[r*QP + u*8] = gvl[idx];
            }
        }
        __syncthreads();

        // S = (Q/8) @ K^T : 8 n-tiles of 8 keys, fp32 frags
        float s[8][4];
        #pragma unroll
        for (int i = 0; i < 8; i++)
            #pragma unroll
            for (int j = 0; j < 4; j++) s[i][j] = 0.f;
        #pragma unroll
        for (int ks = 0; ks < 4; ks++) {
            #pragma unroll
            for (int nt = 0; nt < 8; nt++) {
                uint32_t off = (uint32_t)((nt*8 + (lane & 7))*QP
                               + ks*16 + ((lane >> 3) & 1)*8)*2;
                uint32_t b0, b1, d0, d1;
                ldmx2(b0, b1, sKh + off);
                ldmx2(d0, d1, sKl + off);
                mma_bf16(s[nt], qh[ks], b0, b1);
                mma_bf16(s[nt], qh[ks], d0, d1);
                mma_bf16(s[nt], ql[ks], b0, b1);
            }
        }

        // Online softmax (rows r=lane/4 and r+8; quad = lanes sharing lane/4)
        float mx0 = mr0, mx1 = mr1;
        #pragma unroll
        for (int nt = 0; nt < 8; nt++) {
            mx0 = fmaxf(mx0, fmaxf(s[nt][0], s[nt][1]));
            mx1 = fmaxf(mx1, fmaxf(s[nt][2], s[nt][3]));
        }
        mx0 = fmaxf(mx0, __shfl_xor_sync(0xffffffffu, mx0, 1));
        mx0 = fmaxf(mx0, __shfl_xor_sync(0xffffffffu, mx0, 2));
        mx1 = fmaxf(mx1, __shfl_xor_sync(0xffffffffu, mx1, 1));
        mx1 = fmaxf(mx1, __shfl_xor_sync(0xffffffffu, mx1, 2));
        float al0 = __expf(mr0 - mx0), al1 = __expf(mr1 - mx1);
        mr0 = mx0; mr1 = mx1;

        // P = exp(S - m), built directly as A-frags (hi/lo split)
        uint32_t ph[4][4], pl[4][4];
        float su0 = 0.f, su1 = 0.f;
        #pragma unroll
        for (int nt = 0; nt < 8; nt++) {
            float p0 = __expf(s[nt][0] - mx0);
            float p1 = __expf(s[nt][1] - mx0);
            float p2 = __expf(s[nt][2] - mx1);
            float p3 = __expf(s[nt][3] - mx1);
            su0 += p0 + p1;
            su1 += p2 + p3;
            int kk = nt >> 1, e = (nt & 1)*2;
            uint32_t H, L;
            split_pair(p0, p1, H, L); ph[kk][e]   = H; pl[kk][e]   = L;
            split_pair(p2, p3, H, L); ph[kk][e+1] = H; pl[kk][e+1] = L;
        }
        su0 += __shfl_xor_sync(0xffffffffu, su0, 1);
        su0 += __shfl_xor_sync(0xffffffffu, su0, 2);
        su1 += __shfl_xor_sync(0xffffffffu, su1, 1);
        su1 += __shfl_xor_sync(0xffffffffu, su1, 2);
        lr0 = lr0*al0 + su0;
        lr1 = lr1*al1 + su1;

        #pragma unroll
        for (int nt = 0; nt < 8; nt++) {
            o[nt][0] *= al0; o[nt][1] *= al0;
            o[nt][2] *= al1; o[nt][3] *= al1;
        }

        // O += P @ V  (V via ldmatrix.trans)
        #pragma unroll
        for (int kk = 0; kk < 4; kk++) {
            #pragma unroll
            for (int nt = 0; nt < 8; nt++) {
                uint32_t off = (uint32_t)((kk*16 + (lane & 15))*QP + nt*8)*2;
                uint32_t v0, v1, u0, u1;
                ldmx2t(v0, v1, sVh + off);
                ldmx2t(u0, u1, sVl + off);
                mma_bf16(o[nt], ph[kk], v0, v1);
                mma_bf16(o[nt], ph[kk], u0, u1);
                mma_bf16(o[nt], pl[kk], v0, v1);
            }
        }
    }

    // Epilogue: normalize, split, write to g_O{h,l} [b][seq][768]
    float inv0 = 1.f/lr0, inv1 = 1.f/lr1;
    int r = q0 + w*16 + (lane >> 2);
    #pragma unroll
    for (int nt = 0; nt < 8; nt++) {
        int col = hh*HD + nt*8 + (lane & 3)*2;
        size_t base0 = ((size_t)bb*SEQ + r)*DIM + col;
        size_t base1 = base0 + (size_t)8*DIM;
        uint32_t H, L;
        split_pair(o[nt][0]*inv0, o[nt][1]*inv0, H, L);
        ((uint32_t*)g_Oh)[base0 >> 1] = H;
        ((uint32_t*)g_Ol)[base0 >> 1] = L;
        split_pair(o[nt][2]*inv1, o[nt][3]*inv1, H, L);
        ((uint32_t*)g_Oh)[base1 >> 1] = H;
        ((uint32_t*)g_Ol)[base1 >> 1] = L;
    }
}

// ---------------------------------------------------------------------------
// Proj GEMM: out[16384,768] = O @ Wproj + b  (A already bf16 hi/lo split)
// ---------------------------------------------------------------------------
__global__ __launch_bounds__(256) void proj_gemm(
    const float* __restrict__ W, const float* __restrict__ bias,
    float* __restrict__ out)
{
    __shared__ __align__(16) bf16 Ah[128*AP], Al[128*AP];
    __shared__ __align__(16) bf16 Bh[64*AP],  Bl[64*AP];

    const int tid = threadIdx.x, lane = tid & 31, wid = tid >> 5;
    const int wm = (wid & 3)*32, wn = (wid >> 2)*32;
    const int m0 = blockIdx.y*128;
    const int n0 = blockIdx.x*64;

    float c[2][4][4];
    #pragma unroll
    for (int i = 0; i < 2; i++)
        #pragma unroll
        for (int j = 0; j < 4; j++)
            #pragma unroll
            for (int k = 0; k < 4; k++) c[i][j][k] = 0.f;

    const uint32_t sAh = cvta_s(Ah), sAl = cvta_s(Al);
    const uint32_t sBh = cvta_s(Bh), sBl = cvta_s(Bl);

    for (int k0 = 0; k0 < DIM; k0 += 32) {
        __syncthreads();
        // A: copy bf16 hi/lo tiles directly (already split)
        #pragma unroll
        for (int p = 0; p < 2; p++) {
            int idx = p*256 + tid;
            int r = idx >> 2, u = (idx & 3)*8;
            *(uint4*)&Ah[r*AP + u] =
                *(const uint4*)&g_Oh[(size_t)(m0 + r)*DIM + k0 + u];
            *(uint4*)&Al[r*AP + u] =
                *(const uint4*)&g_Ol[(size_t)(m0 + r)*DIM + k0 + u];
        }
        // B: fp32 Wproj -> transpose-split [n][k]
        #pragma unroll
        for (int p = 0; p < 2; p++) {
            int idx = p*256 + tid;
            int kk = idx >> 4, n4 = (idx & 15)*4;
            float4 v = *(const float4*)&W[(size_t)(k0 + kk)*DIM + n0 + n4];
            bf16 h, l;
            split1(v.x, h, l); Bh[(n4+0)*AP + kk] = h; Bl[(n4+0)*AP + kk] = l;
            split1(v.y, h, l); Bh[(n4+1)*AP + kk] = h; Bl[(n4+1)*AP + kk] = l;
            split1(v.z, h, l); Bh[(n4+2)*AP + kk] = h; Bl[(n4+2)*AP + kk] = l;
            split1(v.w, h, l); Bh[(n4+3)*AP + kk] = h; Bl[(n4+3)*AP + kk] = l;
        }
        __syncthreads();

        #pragma unroll
        for (int ks = 0; ks < 2; ks++) {
            uint32_t ah[2][4], al[2][4];
            #pragma unroll
            for (int mt = 0; mt < 2; mt++) {
                uint32_t off = (uint32_t)((wm + mt*16 + (lane & 15))*AP
                               + ks*16 + ((lane >> 4) & 1)*8)*2;
                ldmx4(ah[mt], sAh + off);
                ldmx4(al[mt], sAl + off);
            }
            #pragma unroll
            for (int nt = 0; nt < 4; nt++) {
                uint32_t off = (uint32_t)((wn + nt*8 + (lane & 7))*AP
                               + ks*16 + ((lane >> 3) & 1)*8)*2;
                uint32_t b0, b1, d0, d1;
                ldmx2(b0, b1, sBh + off);
                ldmx2(d0, d1, sBl + off);
                #pragma unroll
                for (int mt = 0; mt < 2; mt++) {
                    mma_bf16(c[mt][nt], ah[mt], b0, b1);
                    mma_bf16(c[mt][nt], ah[mt], d0, d1);
                    mma_bf16(c[mt][nt], al[mt], b0, b1);
                }
            }
        }
    }

    #pragma unroll
    for (int mt = 0; mt < 2; mt++) {
        int r = m0 + wm + mt*16 + (lane >> 2);
        #pragma unroll
        for (int nt = 0; nt < 4; nt++) {
            int col = n0 + wn + nt*8 + (lane & 3)*2;
            float b0 = bias[col], b1 = bias[col + 1];
            float2 v0 = make_float2(c[mt][nt][0] + b0, c[mt][nt][1] + b1);
            *(float2*)&out[(size_t)r*DIM + col] = v0;
            float2 v1 = make_float2(c[mt][nt][2] + b0, c[mt][nt][3] + b1);
            *(float2*)&out[(size_t)(r + 8)*DIM + col] = v1;
        }
    }
}

// ---------------------------------------------------------------------------
extern "C" void kernel_launch(void* const* d_in, const int* in_sizes, int n_in,
                              void* d_out, int out_size)
{
    (void)in_sizes; (void)n_in; (void)out_size;
    const float* x     = (const float*)d_in[0];
    const float* wqkv  = (const float*)d_in[1];
    const float* bqkv  = (const float*)d_in[2];
    const float* wproj = (const float*)d_in[3];
    const float* bproj = (const float*)d_in[4];
    float* out = (float*)d_out;

    cudaFuncSetAttribute(attn_kernel,
                         cudaFuncAttributeMaxDynamicSharedMemorySize,
                         ATTN_SMEM);

    qkv_gemm<<<dim3(NQKV/64, MTOT/128), 256>>>(x, wqkv, bqkv);        // 36x128
    attn_kernel<<<dim3(SEQ/64, BH), 128, ATTN_SMEM>>>();              // 16x192
    proj_gemm<<<dim3(DIM/64, MTOT/128), 256>>>(wproj, bproj, out);    // 12x128
}